// round 1
// baseline (speedup 1.0000x reference)
#include <cuda_runtime.h>

// PCN_28681791603104 — reduced computation.
//
// Analysis of the reference:
//   * out = S_fin[-1] == initial S[14]  (top layer never updated)  -> pure copy.
//   * Wg_fin depends ONLY on the layer-13 state trajectory:
//       P13 = relu(S14) @ Wk13^T                       (constant, one GEMM)
//       per cycle t = 1..10:
//         E  = S13 - P13
//         G  = Wg^T @ E          (contraction over batch dim:  G[a][b] = sum_c Wg[c][a] E[c][b])
//         S13 += LR * (-E + relu'(S13)) * G            (elementwise)
//         Wg  = LR * E * relu'(S14)^T                  (elementwise, replaces Wg)
//     Wg_fin = Wg after cycle 10.
//   All other layers / inputs (input_data, s0, W1, Wk[0..12], S[0..12]) are dead.
//
// Implementation: single CTA, 512 threads, everything L1/SMEM/register resident.
// GEMMs use packed fma.rn.f32x2 (2 fp32 FMA per instruction on sm_103a).

#define LRV 0.01f
#define NCYC 10

__device__ __forceinline__ unsigned long long pack2(float x) {
    unsigned long long r;
    asm("mov.b64 %0, {%1, %1};" : "=l"(r) : "f"(x));
    return r;
}
__device__ __forceinline__ void fma2(unsigned long long& acc,
                                     unsigned long long a,
                                     unsigned long long b) {
    asm("fma.rn.f32x2 %0, %1, %2, %0;" : "+l"(acc) : "l"(a), "l"(b));
}
__device__ __forceinline__ float2 unpack2(unsigned long long v) {
    float2 f;
    asm("mov.b64 {%0, %1}, %2;" : "=f"(f.x), "=f"(f.y) : "l"(v));
    return f;
}

// Dynamic smem layout (floats):
//   [0,     4096)  : sWg   (current Wg)
//   [4096,  8192)  : sS14
//   [8192, 12288)  : sE
//   [12288,16640)  : sWkT  (Wk13 transposed, row stride 68 floats for bank/16B alignment)
#define SMEM_FLOATS (4096 + 4096 + 4096 + 64 * 68)

extern __shared__ float smem_pool[];

__global__ void __launch_bounds__(512, 1) pcn_kernel(
    const float* __restrict__ S,    // (15,64,64)
    const float* __restrict__ Wk,   // (14,64,64)
    const float* __restrict__ Wg0,  // (64,64)
    float* __restrict__ out,
    int wg_offset)                  // element offset for Wg_fin in out, or -1
{
    float* sWg  = smem_pool;
    float* sS14 = smem_pool + 4096;
    float* sE   = smem_pool + 8192;
    float* sWkT = smem_pool + 12288;

    const int t  = threadIdx.x;
    const int a  = t >> 3;          // owned output row (0..63)
    const int b0 = (t & 7) << 3;    // owned column base (0,8,...,56)

    const float* __restrict__ S13g  = S  + 13 * 4096;
    const float* __restrict__ S14g  = S  + 14 * 4096;
    const float* __restrict__ Wk13g = Wk + 13 * 4096;

    // ---- Prologue: load S14 / Wg, copy out[0:4096] = S14, transpose Wk13 ----
    #pragma unroll
    for (int kk = 0; kk < 8; kk++) {
        int k = t + kk * 512;
        float v = S14g[k];
        sS14[k] = v;
        out[k]  = v;                          // out == initial S[14]
        sWg[k]  = Wg0[k];
        int o = k >> 6, i = k & 63;
        sWkT[i * 68 + o] = Wk13g[k];          // coalesced read, 2-way-conflict write
    }

    // Owned slice of S13 into registers
    float s13[8];
    #pragma unroll
    for (int j = 0; j < 8; j++) s13[j] = S13g[a * 64 + b0 + j];

    __syncthreads();

    // relu'(S14)^T mask (pre-scaled by LR):  m[j] = LR * (S14[b0+j][a] > 0)
    float m[8];
    #pragma unroll
    for (int j = 0; j < 8; j++)
        m[j] = (sS14[(b0 + j) * 64 + a] > 0.0f) ? LRV : 0.0f;

    // ---- P13 GEMM (once): P13[a][b] = sum_i relu(S14[a][i]) * WkT[i][b] ----
    float p13[8];
    {
        unsigned long long acc0 = 0, acc1 = 0, acc2 = 0, acc3 = 0;
        #pragma unroll 4
        for (int i = 0; i < 64; i++) {
            unsigned long long wp = pack2(fmaxf(sS14[a * 64 + i], 0.0f));
            const ulonglong2* ep = (const ulonglong2*)(sWkT + i * 68 + b0);
            ulonglong2 q0 = ep[0];
            ulonglong2 q1 = ep[1];
            fma2(acc0, wp, q0.x);
            fma2(acc1, wp, q0.y);
            fma2(acc2, wp, q1.x);
            fma2(acc3, wp, q1.y);
        }
        float2 f;
        f = unpack2(acc0); p13[0] = f.x; p13[1] = f.y;
        f = unpack2(acc1); p13[2] = f.x; p13[3] = f.y;
        f = unpack2(acc2); p13[4] = f.x; p13[5] = f.y;
        f = unpack2(acc3); p13[6] = f.x; p13[7] = f.y;
    }

    // ---- 10 PCN cycles ----
    const bool write_wg = (wg_offset >= 0);
    #pragma unroll 1
    for (int cyc = 0; cyc < NCYC; cyc++) {
        // E = S13 - P13 (owned elements; publish to smem for the GEMM)
        float e[8];
        #pragma unroll
        for (int j = 0; j < 8; j++) {
            e[j] = s13[j] - p13[j];
            sE[a * 64 + b0 + j] = e[j];
        }
        __syncthreads();   // sE (and previous sWg writes) visible

        // G[a][b0..b0+7] = sum_c Wg[c][a] * E[c][b0..b0+7]
        unsigned long long acc0 = 0, acc1 = 0, acc2 = 0, acc3 = 0;
        #pragma unroll 4
        for (int c = 0; c < 64; c++) {
            unsigned long long wp = pack2(sWg[c * 64 + a]);
            const ulonglong2* ep = (const ulonglong2*)(sE + c * 64 + b0);
            ulonglong2 q0 = ep[0];
            ulonglong2 q1 = ep[1];
            fma2(acc0, wp, q0.x);
            fma2(acc1, wp, q0.y);
            fma2(acc2, wp, q1.x);
            fma2(acc3, wp, q1.y);
        }
        __syncthreads();   // everyone done reading sWg / sE

        float g[8];
        {
            float2 f;
            f = unpack2(acc0); g[0] = f.x; g[1] = f.y;
            f = unpack2(acc1); g[2] = f.x; g[3] = f.y;
            f = unpack2(acc2); g[4] = f.x; g[5] = f.y;
            f = unpack2(acc3); g[6] = f.x; g[7] = f.y;
        }

        // S13 += LR * (relu'(S13) - E) * G ;  Wg <- LR * E * relu'(S14)^T
        #pragma unroll
        for (int j = 0; j < 8; j++) {
            float rp = (s13[j] > 0.0f) ? 1.0f : 0.0f;
            s13[j] = fmaf(LRV * (rp - e[j]), g[j], s13[j]);
            float wnew = e[j] * m[j];               // m already includes LR
            sWg[a * 64 + b0 + j] = wnew;
            if (cyc == NCYC - 1 && write_wg)
                out[wg_offset + a * 64 + b0 + j] = wnew;
        }
        // next-iteration sE write is ordered by the top-of-loop publish + sync
    }
}

extern "C" void kernel_launch(void* const* d_in, const int* in_sizes, int n_in,
                              void* d_out, int out_size) {
    // Identify inputs by element count (unique for the ones we need):
    //   S: 15*64*64 = 61440, Wk: 14*64*64 = 57344, Wg: 4096
    const float* S  = nullptr;
    const float* Wk = nullptr;
    const float* Wg = nullptr;
    for (int i = 0; i < n_in; i++) {
        if (in_sizes[i] == 61440)      S  = (const float*)d_in[i];
        else if (in_sizes[i] == 57344) Wk = (const float*)d_in[i];
        else if (in_sizes[i] == 4096)  Wg = (const float*)d_in[i];
    }

    static bool attr_set = false;
    (void)attr_set;
    cudaFuncSetAttribute(pcn_kernel,
                         cudaFuncAttributeMaxDynamicSharedMemorySize,
                         SMEM_FLOATS * (int)sizeof(float));

    int wg_off = (out_size >= 8192) ? 4096 : -1;
    pcn_kernel<<<1, 512, SMEM_FLOATS * (int)sizeof(float)>>>(
        S, Wk, Wg, (float*)d_out, wg_off);
}